// round 2
// baseline (speedup 1.0000x reference)
#include <cuda_runtime.h>
#include <cstdint>

#define NN 100000
#define NE 1600000
#define D  128
#define NL 3

// Scratch (allocation-free rule: __device__ globals)
__device__ __align__(16) float g_buf0[(size_t)NN * D];
__device__ __align__(16) float g_buf1[(size_t)NN * D];
__device__ __align__(16) float g_agg [(size_t)NN * D];

// ---------------------------------------------------------------------------
// helpers: packed f32x2 math (Blackwell FFMA2 — only reachable via PTX)
// ---------------------------------------------------------------------------
__device__ __forceinline__ unsigned long long pk2(float v) {
    unsigned long long r;
    asm("mov.b64 %0, {%1, %1};" : "=l"(r) : "f"(v));
    return r;
}
__device__ __forceinline__ void upk2(unsigned long long p, float& lo, float& hi) {
    asm("mov.b64 {%0, %1}, %2;" : "=f"(lo), "=f"(hi) : "l"(p));
}
__device__ __forceinline__ void fma2(unsigned long long& d,
                                     unsigned long long a,
                                     unsigned long long b) {
    asm("fma.rn.f32x2 %0, %1, %2, %0;" : "+l"(d) : "l"(a), "l"(b));
}

// ---------------------------------------------------------------------------
// zero kernel (agg init)
// ---------------------------------------------------------------------------
__global__ void zero_kernel(float4* __restrict__ p, int n4) {
    int i = blockIdx.x * blockDim.x + threadIdx.x;
    int stride = gridDim.x * blockDim.x;
    for (; i < n4; i += stride) p[i] = make_float4(0.f, 0.f, 0.f, 0.f);
}

// ---------------------------------------------------------------------------
// scatter: one warp per edge; lane l handles float4 l of the 128-f row.
// red.global.add.v4.f32 -> L2 atomic ALU, 16B granularity.
// ---------------------------------------------------------------------------
__global__ void scatter_kernel(const float* __restrict__ x,
                               const int* __restrict__ src,
                               const int* __restrict__ dst,
                               float* __restrict__ agg) {
    int w = (blockIdx.x * blockDim.x + threadIdx.x) >> 5;
    int lane = threadIdx.x & 31;
    if (w >= NE) return;
    int s = __ldg(src + w);
    int d = __ldg(dst + w);
    const float4* xs = (const float4*)(x + (size_t)s * D);
    float4 v = __ldg(xs + lane);
    float* ap = agg + (size_t)d * D + lane * 4;
    asm volatile("red.global.add.v4.f32 [%0], {%1,%2,%3,%4};"
                 :: "l"(ap), "f"(v.x), "f"(v.y), "f"(v.z), "f"(v.w)
                 : "memory");
}

// ---------------------------------------------------------------------------
// fused MLP: out = [relu]( relu((x+agg) @ W1 + b1) @ W2 + b2 )
// Tile: 128 rows x 128 cols per block, 256 threads, 8x8 outputs/thread,
// f32x2-packed accumulators. W1, W2, A-tile in smem; A-tile reused for H.
// ---------------------------------------------------------------------------
#define TM 128
#define AS_STRIDE 132   // pad: avoid bank conflicts on strided row access

__global__ __launch_bounds__(256, 1)
void mlp_kernel(const float* __restrict__ xin, const float* __restrict__ agg,
                const float* __restrict__ W1, const float* __restrict__ b1,
                const float* __restrict__ W2, const float* __restrict__ b2,
                float* __restrict__ out, int relu_out) {
    extern __shared__ float smem[];
    float* Ws1 = smem;                        // 128*128
    float* Ws2 = Ws1 + D * D;                 // 128*128
    float* As  = Ws2 + D * D;                 // TM * AS_STRIDE
    float* bs1 = As + TM * AS_STRIDE;         // 128
    float* bs2 = bs1 + D;                     // 128

    const int tid = threadIdx.x;

    // cooperative load of weights + biases
    {
        const float4* w1g = (const float4*)W1;
        const float4* w2g = (const float4*)W2;
        float4* w1s = (float4*)Ws1;
        float4* w2s = (float4*)Ws2;
        #pragma unroll
        for (int i = tid; i < D * D / 4; i += 256) {
            w1s[i] = __ldg(w1g + i);
            w2s[i] = __ldg(w2g + i);
        }
        if (tid < D) { bs1[tid] = __ldg(b1 + tid); bs2[tid] = __ldg(b2 + tid); }
    }

    // load A tile = x + agg  (128 rows x 32 float4)
    const int row0 = blockIdx.x * TM;
    for (int i = tid; i < TM * (D / 4); i += 256) {
        int r = i >> 5;
        int c = i & 31;
        int gr = row0 + r;
        float4 v;
        if (gr < NN) {
            const float4* xp = (const float4*)(xin + (size_t)gr * D) + c;
            const float4* ap = (const float4*)(agg + (size_t)gr * D) + c;
            float4 a = __ldg(xp), b = __ldg(ap);
            v = make_float4(a.x + b.x, a.y + b.y, a.z + b.z, a.w + b.w);
        } else {
            v = make_float4(0.f, 0.f, 0.f, 0.f);
        }
        ((float4*)&As[r * AS_STRIDE])[c] = v;
    }
    __syncthreads();

    const int mi = tid >> 4;   // 0..15 -> rows mi*8 .. mi*8+7
    const int ni = tid & 15;   // 0..15 -> cols ni*8 .. ni*8+7

    unsigned long long acc[8][4];

    // GEMM over smem weights Wsm (acc = A_tile @ Wsm)
    auto gemm = [&](const float* __restrict__ Wsm) {
        #pragma unroll
        for (int r = 0; r < 8; r++)
            #pragma unroll
            for (int c = 0; c < 4; c++) acc[r][c] = 0ull;

        const float* abase = As + (mi * 8) * AS_STRIDE;
        #pragma unroll 2
        for (int k = 0; k < D; k += 2) {
            // W rows k and k+1, 8 consecutive cols -> 4 packed pairs each
            ulonglong2 wA0 = *(const ulonglong2*)&Wsm[k * D + ni * 8];
            ulonglong2 wA1 = *(const ulonglong2*)&Wsm[k * D + ni * 8 + 4];
            ulonglong2 wB0 = *(const ulonglong2*)&Wsm[(k + 1) * D + ni * 8];
            ulonglong2 wB1 = *(const ulonglong2*)&Wsm[(k + 1) * D + ni * 8 + 4];
            unsigned long long wk0[4] = {wA0.x, wA0.y, wA1.x, wA1.y};
            unsigned long long wk1[4] = {wB0.x, wB0.y, wB1.x, wB1.y};
            #pragma unroll
            for (int r = 0; r < 8; r++) {
                float2 a = *(const float2*)&abase[r * AS_STRIDE + k]; // broadcast (half-warp same addr)
                unsigned long long a0 = pk2(a.x);
                unsigned long long a1 = pk2(a.y);
                #pragma unroll
                for (int c = 0; c < 4; c++) {
                    fma2(acc[r][c], a0, wk0[c]);
                    fma2(acc[r][c], a1, wk1[c]);
                }
            }
        }
    };

    // ---- GEMM1: H = relu(A @ W1 + b1) ----
    gemm(Ws1);
    __syncthreads();   // everyone done reading As before we overwrite it with H

    #pragma unroll
    for (int r = 0; r < 8; r++) {
        float* drow = &As[(mi * 8 + r) * AS_STRIDE + ni * 8];
        #pragma unroll
        for (int c = 0; c < 4; c++) {
            float lo, hi;
            upk2(acc[r][c], lo, hi);
            int col = ni * 8 + 2 * c;
            lo = fmaxf(lo + bs1[col], 0.f);
            hi = fmaxf(hi + bs1[col + 1], 0.f);
            ((float2*)drow)[c] = make_float2(lo, hi);
        }
    }
    __syncthreads();

    // ---- GEMM2: out = [relu](H @ W2 + b2) ----
    gemm(Ws2);

    #pragma unroll
    for (int r = 0; r < 8; r++) {
        int gr = row0 + mi * 8 + r;
        if (gr >= NN) continue;
        float* orow = out + (size_t)gr * D + ni * 8;
        #pragma unroll
        for (int c = 0; c < 4; c++) {
            float lo, hi;
            upk2(acc[r][c], lo, hi);
            int col = ni * 8 + 2 * c;
            lo += bs2[col];
            hi += bs2[col + 1];
            if (relu_out) { lo = fmaxf(lo, 0.f); hi = fmaxf(hi, 0.f); }
            ((float2*)orow)[c] = make_float2(lo, hi);
        }
    }
}

// ---------------------------------------------------------------------------
// launch
// ---------------------------------------------------------------------------
extern "C" void kernel_launch(void* const* d_in, const int* in_sizes, int n_in,
                              void* d_out, int out_size) {
    const float* x  = (const float*)d_in[0];
    const int*   ei = (const int*)d_in[1];
    const float* W1 = (const float*)d_in[2];
    const float* b1 = (const float*)d_in[3];
    const float* W2 = (const float*)d_in[4];
    const float* b2 = (const float*)d_in[5];
    float* out = (float*)d_out;

    const int* src = ei;
    const int* dst = ei + NE;

    float *p_buf0, *p_buf1, *p_agg;
    cudaGetSymbolAddress((void**)&p_buf0, g_buf0);
    cudaGetSymbolAddress((void**)&p_buf1, g_buf1);
    cudaGetSymbolAddress((void**)&p_agg,  g_agg);

    const size_t smem_bytes = (size_t)(2 * D * D + TM * AS_STRIDE + 2 * D) * sizeof(float);
    cudaFuncSetAttribute(mlp_kernel, cudaFuncAttributeMaxDynamicSharedMemorySize,
                         (int)smem_bytes);

    const int n4 = NN * D / 4;
    const int scat_blocks = (NE * 32 + 255) / 256;
    const int mlp_blocks = (NN + TM - 1) / TM;

    const float* lin[3]  = {x, p_buf0, p_buf1};
    float*       lout[3] = {p_buf0, p_buf1, out};

    for (int l = 0; l < NL; l++) {
        zero_kernel<<<1024, 256>>>((float4*)p_agg, n4);
        scatter_kernel<<<scat_blocks, 256>>>(lin[l], src, dst, p_agg);
        mlp_kernel<<<mlp_blocks, 256, smem_bytes>>>(
            lin[l], p_agg,
            W1 + (size_t)l * D * D, b1 + (size_t)l * D,
            W2 + (size_t)l * D * D, b2 + (size_t)l * D,
            lout[l], (l < NL - 1) ? 1 : 0);
    }
    (void)in_sizes; (void)n_in; (void)out_size;
}

// round 3
// speedup vs baseline: 1.4432x; 1.4432x over previous
#include <cuda_runtime.h>
#include <cstdint>

#define NN 100000
#define NE 1600000
#define D  128
#define NL 3
#define NB_SCAN ((NN + 1023) / 1024)   // 98

// Scratch (allocation-free rule: __device__ globals)
__device__ __align__(16) float g_buf0[(size_t)NN * D];
__device__ __align__(16) float g_buf1[(size_t)NN * D];
__device__ __align__(16) float g_h   [(size_t)NN * D];   // x + agg, MLP input
__device__ int g_deg[NN];
__device__ int g_rows[NN + 1];
__device__ int g_cursor[NN];
__device__ int g_bsum[NB_SCAN];
__device__ int g_boff[NB_SCAN];
__device__ int g_srcs[NE];

// ---------------------------------------------------------------------------
// packed f32x2 math (Blackwell FFMA2 — only reachable via PTX)
// ---------------------------------------------------------------------------
__device__ __forceinline__ unsigned long long pk2(float v) {
    unsigned long long r;
    asm("mov.b64 %0, {%1, %1};" : "=l"(r) : "f"(v));
    return r;
}
__device__ __forceinline__ void upk2(unsigned long long p, float& lo, float& hi) {
    asm("mov.b64 {%0, %1}, %2;" : "=f"(lo), "=f"(hi) : "l"(p));
}
__device__ __forceinline__ void fma2(unsigned long long& d,
                                     unsigned long long a,
                                     unsigned long long b) {
    asm("fma.rn.f32x2 %0, %1, %2, %0;" : "+l"(d) : "l"(a), "l"(b));
}

// ---------------------------------------------------------------------------
// CSR build: histogram -> scan -> fill
// ---------------------------------------------------------------------------
__global__ void hist_kernel(const int* __restrict__ dst, int* __restrict__ deg) {
    int i = blockIdx.x * blockDim.x + threadIdx.x;
    if (i < NE) atomicAdd(&deg[__ldg(dst + i)], 1);
}

// block b scans 1024 elems; writes per-element exclusive (within block) + block total
__global__ void scan1_kernel(const int* __restrict__ deg, int* __restrict__ rows,
                             int* __restrict__ bsum) {
    __shared__ int ts[256];
    const int t = threadIdx.x;
    const int base = blockIdx.x * 1024 + t * 4;
    int v[4], s = 0;
    #pragma unroll
    for (int i = 0; i < 4; i++) {
        v[i] = (base + i < NN) ? deg[base + i] : 0;
        s += v[i];
    }
    ts[t] = s;
    __syncthreads();
    // inclusive Hillis-Steele over 256 thread sums
    #pragma unroll
    for (int off = 1; off < 256; off <<= 1) {
        int x = (t >= off) ? ts[t - off] : 0;
        __syncthreads();
        ts[t] += x;
        __syncthreads();
    }
    int run = ts[t] - s;  // exclusive thread offset
    #pragma unroll
    for (int i = 0; i < 4; i++) {
        if (base + i < NN) rows[base + i] = run;
        run += v[i];
    }
    if (t == 255) bsum[blockIdx.x] = ts[255];
}

__global__ void scan2_kernel(const int* __restrict__ bsum, int* __restrict__ boff) {
    __shared__ int s[128];
    const int t = threadIdx.x;   // 128 threads
    int orig = (t < NB_SCAN) ? bsum[t] : 0;
    s[t] = orig;
    __syncthreads();
    #pragma unroll
    for (int off = 1; off < 128; off <<= 1) {
        int x = (t >= off) ? s[t - off] : 0;
        __syncthreads();
        s[t] += x;
        __syncthreads();
    }
    if (t < NB_SCAN) boff[t] = s[t] - orig;  // exclusive
}

__global__ void scan3_kernel(int* __restrict__ rows, const int* __restrict__ boff) {
    int i = blockIdx.x * blockDim.x + threadIdx.x;
    if (i < NN) rows[i] += boff[i >> 10];
    if (i == 0) rows[NN] = NE;
}

__global__ void fill_kernel(const int* __restrict__ src, const int* __restrict__ dst,
                            int* __restrict__ cursor, int* __restrict__ srcs) {
    int i = blockIdx.x * blockDim.x + threadIdx.x;
    if (i < NE) {
        int d = __ldg(dst + i);
        int pos = atomicAdd(&cursor[d], 1);
        srcs[pos] = __ldg(src + i);
    }
}

// ---------------------------------------------------------------------------
// pull-mode gather-sum: one warp per node, h[n] = x[n] + sum_{e in N(n)} x[src_e]
// ---------------------------------------------------------------------------
__global__ __launch_bounds__(256)
void gather_kernel(const float* __restrict__ x, const int* __restrict__ rows,
                   const int* __restrict__ srcs, float* __restrict__ h) {
    const int n = (blockIdx.x * blockDim.x + threadIdx.x) >> 5;
    if (n >= NN) return;
    const int lane = threadIdx.x & 31;
    const float4* x4 = (const float4*)x;
    float4 acc = __ldg(x4 + (size_t)n * 32 + lane);
    int e = __ldg(rows + n);
    const int end = __ldg(rows + n + 1);
    while (e < end) {
        int cnt = min(32, end - e);
        int sv = (lane < cnt) ? __ldg(srcs + e + lane) : 0;
        int j = 0;
        for (; j + 4 <= cnt; j += 4) {
            int s0 = __shfl_sync(0xffffffff, sv, j + 0);
            int s1 = __shfl_sync(0xffffffff, sv, j + 1);
            int s2 = __shfl_sync(0xffffffff, sv, j + 2);
            int s3 = __shfl_sync(0xffffffff, sv, j + 3);
            float4 v0 = __ldg(x4 + (size_t)s0 * 32 + lane);
            float4 v1 = __ldg(x4 + (size_t)s1 * 32 + lane);
            float4 v2 = __ldg(x4 + (size_t)s2 * 32 + lane);
            float4 v3 = __ldg(x4 + (size_t)s3 * 32 + lane);
            acc.x += v0.x; acc.y += v0.y; acc.z += v0.z; acc.w += v0.w;
            acc.x += v1.x; acc.y += v1.y; acc.z += v1.z; acc.w += v1.w;
            acc.x += v2.x; acc.y += v2.y; acc.z += v2.z; acc.w += v2.w;
            acc.x += v3.x; acc.y += v3.y; acc.z += v3.z; acc.w += v3.w;
        }
        for (; j < cnt; j++) {
            int s = __shfl_sync(0xffffffff, sv, j);
            float4 v = __ldg(x4 + (size_t)s * 32 + lane);
            acc.x += v.x; acc.y += v.y; acc.z += v.z; acc.w += v.w;
        }
        e += cnt;
    }
    ((float4*)h)[(size_t)n * 32 + lane] = acc;
}

// ---------------------------------------------------------------------------
// fused MLP: out = [relu]( relu(h @ W1 + b1) @ W2 + b2 )
// 128x128 tile / block, 256 threads, 8x8 outputs/thread, f32x2 accumulators
// ---------------------------------------------------------------------------
#define TM 128
#define AS_STRIDE 132

__global__ __launch_bounds__(256, 1)
void mlp_kernel(const float* __restrict__ hin,
                const float* __restrict__ W1, const float* __restrict__ b1,
                const float* __restrict__ W2, const float* __restrict__ b2,
                float* __restrict__ out, int relu_out) {
    extern __shared__ float smem[];
    float* Ws1 = smem;                        // 128*128
    float* Ws2 = Ws1 + D * D;                 // 128*128
    float* As  = Ws2 + D * D;                 // TM * AS_STRIDE
    float* bs1 = As + TM * AS_STRIDE;         // 128
    float* bs2 = bs1 + D;                     // 128

    const int tid = threadIdx.x;

    {
        const float4* w1g = (const float4*)W1;
        const float4* w2g = (const float4*)W2;
        float4* w1s = (float4*)Ws1;
        float4* w2s = (float4*)Ws2;
        #pragma unroll
        for (int i = tid; i < D * D / 4; i += 256) {
            w1s[i] = __ldg(w1g + i);
            w2s[i] = __ldg(w2g + i);
        }
        if (tid < D) { bs1[tid] = __ldg(b1 + tid); bs2[tid] = __ldg(b2 + tid); }
    }

    const int row0 = blockIdx.x * TM;
    for (int i = tid; i < TM * (D / 4); i += 256) {
        int r = i >> 5;
        int c = i & 31;
        int gr = row0 + r;
        float4 v = make_float4(0.f, 0.f, 0.f, 0.f);
        if (gr < NN) v = __ldg((const float4*)(hin + (size_t)gr * D) + c);
        ((float4*)&As[r * AS_STRIDE])[c] = v;
    }
    __syncthreads();

    const int mi = tid >> 4;
    const int ni = tid & 15;

    unsigned long long acc[8][4];

    auto gemm = [&](const float* __restrict__ Wsm) {
        #pragma unroll
        for (int r = 0; r < 8; r++)
            #pragma unroll
            for (int c = 0; c < 4; c++) acc[r][c] = 0ull;

        const float* abase = As + (mi * 8) * AS_STRIDE;
        #pragma unroll 2
        for (int k = 0; k < D; k += 2) {
            ulonglong2 wA0 = *(const ulonglong2*)&Wsm[k * D + ni * 8];
            ulonglong2 wA1 = *(const ulonglong2*)&Wsm[k * D + ni * 8 + 4];
            ulonglong2 wB0 = *(const ulonglong2*)&Wsm[(k + 1) * D + ni * 8];
            ulonglong2 wB1 = *(const ulonglong2*)&Wsm[(k + 1) * D + ni * 8 + 4];
            unsigned long long wk0[4] = {wA0.x, wA0.y, wA1.x, wA1.y};
            unsigned long long wk1[4] = {wB0.x, wB0.y, wB1.x, wB1.y};
            #pragma unroll
            for (int r = 0; r < 8; r++) {
                float2 a = *(const float2*)&abase[r * AS_STRIDE + k];
                unsigned long long a0 = pk2(a.x);
                unsigned long long a1 = pk2(a.y);
                #pragma unroll
                for (int c = 0; c < 4; c++) {
                    fma2(acc[r][c], a0, wk0[c]);
                    fma2(acc[r][c], a1, wk1[c]);
                }
            }
        }
    };

    // ---- GEMM1: H = relu(A @ W1 + b1), stored back into As ----
    gemm(Ws1);
    __syncthreads();

    #pragma unroll
    for (int r = 0; r < 8; r++) {
        float* drow = &As[(mi * 8 + r) * AS_STRIDE + ni * 8];
        #pragma unroll
        for (int c = 0; c < 4; c++) {
            float lo, hi;
            upk2(acc[r][c], lo, hi);
            int col = ni * 8 + 2 * c;
            lo = fmaxf(lo + bs1[col], 0.f);
            hi = fmaxf(hi + bs1[col + 1], 0.f);
            ((float2*)drow)[c] = make_float2(lo, hi);
        }
    }
    __syncthreads();

    // ---- GEMM2: out = [relu](H @ W2 + b2) ----
    gemm(Ws2);

    #pragma unroll
    for (int r = 0; r < 8; r++) {
        int gr = row0 + mi * 8 + r;
        if (gr >= NN) continue;
        float* orow = out + (size_t)gr * D + ni * 8;
        #pragma unroll
        for (int c = 0; c < 4; c++) {
            float lo, hi;
            upk2(acc[r][c], lo, hi);
            int col = ni * 8 + 2 * c;
            lo += bs2[col];
            hi += bs2[col + 1];
            if (relu_out) { lo = fmaxf(lo, 0.f); hi = fmaxf(hi, 0.f); }
            ((float2*)orow)[c] = make_float2(lo, hi);
        }
    }
}

// ---------------------------------------------------------------------------
// launch
// ---------------------------------------------------------------------------
extern "C" void kernel_launch(void* const* d_in, const int* in_sizes, int n_in,
                              void* d_out, int out_size) {
    const float* x  = (const float*)d_in[0];
    const int*   ei = (const int*)d_in[1];
    const float* W1 = (const float*)d_in[2];
    const float* b1 = (const float*)d_in[3];
    const float* W2 = (const float*)d_in[4];
    const float* b2 = (const float*)d_in[5];
    float* out = (float*)d_out;

    const int* src = ei;
    const int* dst = ei + NE;

    float *p_buf0, *p_buf1, *p_h;
    int *p_deg, *p_rows, *p_cursor, *p_bsum, *p_boff, *p_srcs;
    cudaGetSymbolAddress((void**)&p_buf0,   g_buf0);
    cudaGetSymbolAddress((void**)&p_buf1,   g_buf1);
    cudaGetSymbolAddress((void**)&p_h,      g_h);
    cudaGetSymbolAddress((void**)&p_deg,    g_deg);
    cudaGetSymbolAddress((void**)&p_rows,   g_rows);
    cudaGetSymbolAddress((void**)&p_cursor, g_cursor);
    cudaGetSymbolAddress((void**)&p_bsum,   g_bsum);
    cudaGetSymbolAddress((void**)&p_boff,   g_boff);
    cudaGetSymbolAddress((void**)&p_srcs,   g_srcs);

    const size_t smem_bytes = (size_t)(2 * D * D + TM * AS_STRIDE + 2 * D) * sizeof(float);
    cudaFuncSetAttribute(mlp_kernel, cudaFuncAttributeMaxDynamicSharedMemorySize,
                         (int)smem_bytes);

    // ---- CSR build (once per call) ----
    cudaMemsetAsync(p_deg, 0, NN * sizeof(int));
    hist_kernel<<<(NE + 255) / 256, 256>>>(dst, p_deg);
    scan1_kernel<<<NB_SCAN, 256>>>(p_deg, p_rows, p_bsum);
    scan2_kernel<<<1, 128>>>(p_bsum, p_boff);
    scan3_kernel<<<(NN + 255) / 256, 256>>>(p_rows, p_boff);
    cudaMemcpyAsync(p_cursor, p_rows, NN * sizeof(int), cudaMemcpyDeviceToDevice);
    fill_kernel<<<(NE + 255) / 256, 256>>>(src, dst, p_cursor, p_srcs);

    // ---- layers ----
    const int gat_blocks = (NN * 32 + 255) / 256;
    const int mlp_blocks = (NN + TM - 1) / TM;

    const float* lin[3]  = {x, p_buf0, p_buf1};
    float*       lout[3] = {p_buf0, p_buf1, out};

    for (int l = 0; l < NL; l++) {
        gather_kernel<<<gat_blocks, 256>>>(lin[l], p_rows, p_srcs, p_h);
        mlp_kernel<<<mlp_blocks, 256, smem_bytes>>>(
            p_h,
            W1 + (size_t)l * D * D, b1 + (size_t)l * D,
            W2 + (size_t)l * D * D, b2 + (size_t)l * D,
            lout[l], (l < NL - 1) ? 1 : 0);
    }
    (void)in_sizes; (void)n_in; (void)out_size;
}

// round 5
// speedup vs baseline: 1.9099x; 1.3233x over previous
#include <cuda_runtime.h>
#include <cstdint>

#define NN 100000
#define NE 1600000
#define D  128
#define NL 3
#define NB_SCAN ((NN + 1023) / 1024)   // 98
#define NTILES ((NN + 127) / 128)      // 782
#define AST 130                         // As stride: 4*AST*4B = 2080B ≡ 8B mod 128B -> conflict-free

// Scratch (allocation-free rule: __device__ globals)
__device__ __align__(16) float g_buf0[(size_t)NN * D];
__device__ __align__(16) float g_buf1[(size_t)NN * D];
__device__ __align__(16) float g_h   [(size_t)NN * D];
__device__ int g_deg[NN];
__device__ int g_rows[NN + 1];
__device__ int g_cursor[NN];
__device__ int g_bsum[NB_SCAN];
__device__ int g_boff[NB_SCAN];
__device__ int g_srcs[NE];

// ---------------------------------------------------------------------------
// packed f32x2 math (Blackwell FFMA2 — only reachable via PTX)
// ---------------------------------------------------------------------------
__device__ __forceinline__ unsigned long long pk2(float v) {
    unsigned long long r;
    asm("mov.b64 %0, {%1, %1};" : "=l"(r) : "f"(v));
    return r;
}
__device__ __forceinline__ void upk2(unsigned long long p, float& lo, float& hi) {
    asm("mov.b64 {%0, %1}, %2;" : "=f"(lo), "=f"(hi) : "l"(p));
}
__device__ __forceinline__ void fma2(unsigned long long& d,
                                     unsigned long long a,
                                     unsigned long long b) {
    asm("fma.rn.f32x2 %0, %1, %2, %0;" : "+l"(d) : "l"(a), "l"(b));
}

// ---------------------------------------------------------------------------
// CSR build: histogram -> scan -> fill
// ---------------------------------------------------------------------------
__global__ void hist_kernel(const int* __restrict__ dst, int* __restrict__ deg) {
    int i = blockIdx.x * blockDim.x + threadIdx.x;
    if (i < NE) atomicAdd(&deg[__ldg(dst + i)], 1);
}

__global__ void scan1_kernel(const int* __restrict__ deg, int* __restrict__ rows,
                             int* __restrict__ bsum) {
    __shared__ int ts[256];
    const int t = threadIdx.x;
    const int base = blockIdx.x * 1024 + t * 4;
    int v[4], s = 0;
    #pragma unroll
    for (int i = 0; i < 4; i++) {
        v[i] = (base + i < NN) ? deg[base + i] : 0;
        s += v[i];
    }
    ts[t] = s;
    __syncthreads();
    #pragma unroll
    for (int off = 1; off < 256; off <<= 1) {
        int x = (t >= off) ? ts[t - off] : 0;
        __syncthreads();
        ts[t] += x;
        __syncthreads();
    }
    int run = ts[t] - s;
    #pragma unroll
    for (int i = 0; i < 4; i++) {
        if (base + i < NN) rows[base + i] = run;
        run += v[i];
    }
    if (t == 255) bsum[blockIdx.x] = ts[255];
}

__global__ void scan2_kernel(const int* __restrict__ bsum, int* __restrict__ boff) {
    __shared__ int s[128];
    const int t = threadIdx.x;
    int orig = (t < NB_SCAN) ? bsum[t] : 0;
    s[t] = orig;
    __syncthreads();
    #pragma unroll
    for (int off = 1; off < 128; off <<= 1) {
        int x = (t >= off) ? s[t - off] : 0;
        __syncthreads();
        s[t] += x;
        __syncthreads();
    }
    if (t < NB_SCAN) boff[t] = s[t] - orig;
}

__global__ void scan3_kernel(int* __restrict__ rows, const int* __restrict__ boff) {
    int i = blockIdx.x * blockDim.x + threadIdx.x;
    if (i < NN) rows[i] += boff[i >> 10];
    if (i == 0) rows[NN] = NE;
}

__global__ void fill_kernel(const int* __restrict__ src, const int* __restrict__ dst,
                            int* __restrict__ cursor, int* __restrict__ srcs) {
    int i = blockIdx.x * blockDim.x + threadIdx.x;
    if (i < NE) {
        int d = __ldg(dst + i);
        int pos = atomicAdd(&cursor[d], 1);
        srcs[pos] = __ldg(src + i);
    }
}

// ---------------------------------------------------------------------------
// pull-mode gather-sum: one warp per node, h[n] = x[n] + sum x[src_e]
// ---------------------------------------------------------------------------
__global__ __launch_bounds__(256)
void gather_kernel(const float* __restrict__ x, const int* __restrict__ rows,
                   const int* __restrict__ srcs, float* __restrict__ h) {
    const int n = (blockIdx.x * blockDim.x + threadIdx.x) >> 5;
    if (n >= NN) return;
    const int lane = threadIdx.x & 31;
    const float4* x4 = (const float4*)x;
    float4 acc = __ldg(x4 + (size_t)n * 32 + lane);
    int e = __ldg(rows + n);
    const int end = __ldg(rows + n + 1);
    while (e < end) {
        int cnt = min(32, end - e);
        int sv = (lane < cnt) ? __ldg(srcs + e + lane) : 0;
        int j = 0;
        for (; j + 4 <= cnt; j += 4) {
            int s0 = __shfl_sync(0xffffffff, sv, j + 0);
            int s1 = __shfl_sync(0xffffffff, sv, j + 1);
            int s2 = __shfl_sync(0xffffffff, sv, j + 2);
            int s3 = __shfl_sync(0xffffffff, sv, j + 3);
            float4 v0 = __ldg(x4 + (size_t)s0 * 32 + lane);
            float4 v1 = __ldg(x4 + (size_t)s1 * 32 + lane);
            float4 v2 = __ldg(x4 + (size_t)s2 * 32 + lane);
            float4 v3 = __ldg(x4 + (size_t)s3 * 32 + lane);
            acc.x += v0.x; acc.y += v0.y; acc.z += v0.z; acc.w += v0.w;
            acc.x += v1.x; acc.y += v1.y; acc.z += v1.z; acc.w += v1.w;
            acc.x += v2.x; acc.y += v2.y; acc.z += v2.z; acc.w += v2.w;
            acc.x += v3.x; acc.y += v3.y; acc.z += v3.z; acc.w += v3.w;
        }
        for (; j < cnt; j++) {
            int s = __shfl_sync(0xffffffff, sv, j);
            float4 v = __ldg(x4 + (size_t)s * 32 + lane);
            acc.x += v.x; acc.y += v.y; acc.z += v.z; acc.w += v.w;
        }
        e += cnt;
    }
    ((float4*)h)[(size_t)n * 32 + lane] = acc;
}

// ---------------------------------------------------------------------------
// persistent fused MLP: out = [relu]( relu(h @ W1 + b1) @ W2 + b2 )
// 148 CTAs x 512 threads. Warp wd owns cols [wd*8, wd*8+8); lane owns rows
// {lane, lane+32, lane+64, lane+96}. W-loads broadcast; A-loads conflict-free
// (AST=130). FFMA2 packed accumulators (col pairs).
// ---------------------------------------------------------------------------
__global__ __launch_bounds__(512, 1)
void mlp_kernel(const float* __restrict__ hin,
                const float* __restrict__ W1, const float* __restrict__ b1,
                const float* __restrict__ W2, const float* __restrict__ b2,
                float* __restrict__ out, int relu_out) {
    extern __shared__ float smem[];
    float* Ws1 = smem;                 // 128*128
    float* Ws2 = Ws1 + D * D;          // 128*128
    float* As  = Ws2 + D * D;          // 128*AST
    float* bs1 = As + 128 * AST;       // 128
    float* bs2 = bs1 + D;              // 128

    const int tid  = threadIdx.x;
    const int lane = tid & 31;
    const int wd   = tid >> 5;         // 0..15 : col group

    // load weights + biases once (persistent)
    {
        const float4* w1g = (const float4*)W1;
        const float4* w2g = (const float4*)W2;
        float4* w1s = (float4*)Ws1;
        float4* w2s = (float4*)Ws2;
        for (int i = tid; i < D * D / 4; i += 512) {
            w1s[i] = __ldg(w1g + i);
            w2s[i] = __ldg(w2g + i);
        }
        if (tid < D) { bs1[tid] = __ldg(b1 + tid); bs2[tid] = __ldg(b2 + tid); }
    }
    __syncthreads();

    unsigned long long acc[4][4];

    auto gemm = [&](const float* __restrict__ Wsm) {
        #pragma unroll
        for (int r = 0; r < 4; r++)
            #pragma unroll
            for (int c = 0; c < 4; c++) acc[r][c] = 0ull;

        const float* arow = As + lane * AST;
        const float* wcol = Wsm + wd * 8;
        #pragma unroll 4
        for (int k = 0; k < D; k += 2) {
            ulonglong2 wA0 = *(const ulonglong2*)&wcol[k * D];
            ulonglong2 wA1 = *(const ulonglong2*)&wcol[k * D + 4];
            ulonglong2 wB0 = *(const ulonglong2*)&wcol[(k + 1) * D];
            ulonglong2 wB1 = *(const ulonglong2*)&wcol[(k + 1) * D + 4];
            unsigned long long wk0[4] = {wA0.x, wA0.y, wA1.x, wA1.y};
            unsigned long long wk1[4] = {wB0.x, wB0.y, wB1.x, wB1.y};
            #pragma unroll
            for (int r = 0; r < 4; r++) {
                float2 a = *(const float2*)&arow[r * 32 * AST + k];
                unsigned long long a0 = pk2(a.x);
                unsigned long long a1 = pk2(a.y);
                #pragma unroll
                for (int c = 0; c < 4; c++) {
                    fma2(acc[r][c], a0, wk0[c]);
                    fma2(acc[r][c], a1, wk1[c]);
                }
            }
        }
    };

    for (int tile = blockIdx.x; tile < NTILES; tile += gridDim.x) {
        const int row0 = tile * 128;

        // ---- A tile load (coalesced; warp = one row) ----
        for (int i = tid; i < 128 * 32; i += 512) {
            int r = i >> 5;
            int c = i & 31;
            int gr = row0 + r;
            float4 v = make_float4(0.f, 0.f, 0.f, 0.f);
            if (gr < NN) v = __ldg((const float4*)(hin + (size_t)gr * D) + c);
            float* p = &As[r * AST + c * 4];
            ((float2*)p)[0] = make_float2(v.x, v.y);
            ((float2*)p)[1] = make_float2(v.z, v.w);
        }
        __syncthreads();

        // ---- GEMM1 ----
        gemm(Ws1);
        __syncthreads();

        // ---- epilogue 1: H = relu(acc + b1) -> As ----
        #pragma unroll
        for (int r = 0; r < 4; r++) {
            float* hrow = &As[(lane + r * 32) * AST + wd * 8];
            #pragma unroll
            for (int c = 0; c < 4; c++) {
                float lo, hi;
                upk2(acc[r][c], lo, hi);
                int col = wd * 8 + 2 * c;
                lo = fmaxf(lo + bs1[col], 0.f);
                hi = fmaxf(hi + bs1[col + 1], 0.f);
                ((float2*)hrow)[c] = make_float2(lo, hi);
            }
        }
        __syncthreads();

        // ---- GEMM2 ----
        gemm(Ws2);
        __syncthreads();

        // ---- epilogue 2: [relu](acc + b2) -> As (for coalesced store) ----
        #pragma unroll
        for (int r = 0; r < 4; r++) {
            float* orow = &As[(lane + r * 32) * AST + wd * 8];
            #pragma unroll
            for (int c = 0; c < 4; c++) {
                float lo, hi;
                upk2(acc[r][c], lo, hi);
                int col = wd * 8 + 2 * c;
                lo += bs2[col];
                hi += bs2[col + 1];
                if (relu_out) { lo = fmaxf(lo, 0.f); hi = fmaxf(hi, 0.f); }
                ((float2*)orow)[c] = make_float2(lo, hi);
            }
        }
        __syncthreads();

        // ---- coalesced global store ----
        for (int i = tid; i < 128 * 32; i += 512) {
            int r = i >> 5;
            int c = i & 31;
            int gr = row0 + r;
            if (gr < NN) {
                const float* p = &As[r * AST + c * 4];
                float2 u = ((const float2*)p)[0];
                float2 w = ((const float2*)p)[1];
                ((float4*)(out + (size_t)gr * D))[c] = make_float4(u.x, u.y, w.x, w.y);
            }
        }
        __syncthreads();   // protect As before next tile's A-load
    }
}

// ---------------------------------------------------------------------------
// launch
// ---------------------------------------------------------------------------
extern "C" void kernel_launch(void* const* d_in, const int* in_sizes, int n_in,
                              void* d_out, int out_size) {
    const float* x  = (const float*)d_in[0];
    const int*   ei = (const int*)d_in[1];
    const float* W1 = (const float*)d_in[2];
    const float* b1 = (const float*)d_in[3];
    const float* W2 = (const float*)d_in[4];
    const float* b2 = (const float*)d_in[5];
    float* out = (float*)d_out;

    const int* src = ei;
    const int* dst = ei + NE;

    float *p_buf0, *p_buf1, *p_h;
    int *p_deg, *p_rows, *p_cursor, *p_bsum, *p_boff, *p_srcs;
    cudaGetSymbolAddress((void**)&p_buf0,   g_buf0);
    cudaGetSymbolAddress((void**)&p_buf1,   g_buf1);
    cudaGetSymbolAddress((void**)&p_h,      g_h);
    cudaGetSymbolAddress((void**)&p_deg,    g_deg);
    cudaGetSymbolAddress((void**)&p_rows,   g_rows);
    cudaGetSymbolAddress((void**)&p_cursor, g_cursor);
    cudaGetSymbolAddress((void**)&p_bsum,   g_bsum);
    cudaGetSymbolAddress((void**)&p_boff,   g_boff);
    cudaGetSymbolAddress((void**)&p_srcs,   g_srcs);

    const size_t smem_bytes = (size_t)(2 * D * D + 128 * AST + 2 * D) * sizeof(float);
    cudaFuncSetAttribute(mlp_kernel, cudaFuncAttributeMaxDynamicSharedMemorySize,
                         (int)smem_bytes);

    // ---- CSR build (once per call) ----
    cudaMemsetAsync(p_deg, 0, NN * sizeof(int));
    hist_kernel<<<(NE + 255) / 256, 256>>>(dst, p_deg);
    scan1_kernel<<<NB_SCAN, 256>>>(p_deg, p_rows, p_bsum);
    scan2_kernel<<<1, 128>>>(p_bsum, p_boff);
    scan3_kernel<<<(NN + 255) / 256, 256>>>(p_rows, p_boff);
    cudaMemcpyAsync(p_cursor, p_rows, NN * sizeof(int), cudaMemcpyDeviceToDevice);
    fill_kernel<<<(NE + 255) / 256, 256>>>(src, dst, p_cursor, p_srcs);

    // ---- layers ----
    const int gat_blocks = (NN * 32 + 255) / 256;

    const float* lin[3]  = {x, p_buf0, p_buf1};
    float*       lout[3] = {p_buf0, p_buf1, out};

    for (int l = 0; l < NL; l++) {
        gather_kernel<<<gat_blocks, 256>>>(lin[l], p_rows, p_srcs, p_h);
        mlp_kernel<<<148, 512, smem_bytes>>>(
            p_h,
            W1 + (size_t)l * D * D, b1 + (size_t)l * D,
            W2 + (size_t)l * D * D, b2 + (size_t)l * D,
            lout[l], (l < NL - 1) ? 1 : 0);
    }
    (void)in_sizes; (void)n_in; (void)out_size;
}